// round 3
// baseline (speedup 1.0000x reference)
#include <cuda_runtime.h>
#include <cuda_bf16.h>
#include <math_constants.h>

// Problem constants (fixed shapes for this problem instance)
#define B_DIM 8
#define N_DIM 65536
#define C_DIM 80
#define NTOT (B_DIM * N_DIM)          // 524288 = 2^19
#define TOPK 4096
#define CONF_TH 4.0f
#define NMS_TH 0.5f

// ---------------- device scratch (no allocation allowed) ----------------
__device__ unsigned int        g_cnt;
__device__ unsigned long long  g_keys[TOPK];
__device__ int                 g_M;
__device__ float4              g_sbox[TOPK];
__device__ int                 g_scat[TOPK];
__device__ int                 g_sim[TOPK];
__device__ int                 g_scls[TOPK];
__device__ float               g_ssc[TOPK];
__device__ unsigned long long  g_mask[(size_t)TOPK * 64];   // 2 MB, only M*ceil(M/64) used

// ---------------- kernel 0: reset counter ----------------
__global__ void k_init() {
    g_cnt = 0u;
}

// ---------------- kernel 1: per-anchor max/argmax + threshold compaction ----
// One warp per anchor. 80 classes -> lanes read c=lane, c=lane+32, (lane<16) c=lane+64.
__device__ __forceinline__ void comb(float& s, int& c, float s2, int c2) {
    // max score, tie-break lower class (jnp.argmax semantics)
    if (s2 > s || (s2 == s && c2 < c)) { s = s2; c = c2; }
}

__global__ void __launch_bounds__(256) k_reduce(const float* __restrict__ logits) {
    int wid  = (blockIdx.x * blockDim.x + threadIdx.x) >> 5;
    int lane = threadIdx.x & 31;
    if (wid >= NTOT) return;

    const float* p = logits + (size_t)wid * C_DIM;
    float s = __ldcs(p + lane);
    int   c = lane;
    comb(s, c, __ldcs(p + lane + 32), lane + 32);
    if (lane < 16) comb(s, c, __ldcs(p + lane + 64), lane + 64);

    #pragma unroll
    for (int off = 16; off > 0; off >>= 1) {
        float s2 = __shfl_down_sync(0xFFFFFFFFu, s, off);
        int   c2 = __shfl_down_sync(0xFFFFFFFFu, c, off);
        comb(s, c, s2, c2);
    }

    if (lane == 0 && s > CONF_TH) {
        unsigned pos = atomicAdd(&g_cnt, 1u);
        if (pos < TOPK) {
            unsigned long long key =
                ((unsigned long long)__float_as_uint(s) << 32) |
                ((unsigned long long)(unsigned)((NTOT - 1) - wid) << 7) |
                (unsigned long long)(unsigned)c;
            g_keys[pos] = key;
        }
    }
}

// ---------------- kernel 2: bitonic sort (descending) + gather sorted arrays --
__global__ void __launch_bounds__(1024) k_sort(const float* __restrict__ boxes) {
    __shared__ unsigned long long sk[TOPK];
    int t = threadIdx.x;
    int M = (int)min(g_cnt, (unsigned)TOPK);

    for (int i = t; i < TOPK; i += 1024)
        sk[i] = (i < M) ? g_keys[i] : 0ULL;
    __syncthreads();

    for (int k = 2; k <= TOPK; k <<= 1) {
        for (int j = k >> 1; j > 0; j >>= 1) {
            for (int i = t; i < TOPK; i += 1024) {
                int ixj = i ^ j;
                if (ixj > i) {
                    unsigned long long a = sk[i], b = sk[ixj];
                    bool seg = ((i & k) == 0);         // descending segment
                    if ((a < b) == seg) { sk[i] = b; sk[ixj] = a; }
                }
            }
            __syncthreads();
        }
    }

    for (int i = t; i < TOPK; i += 1024) {
        unsigned long long key = sk[i];
        if (key != 0ULL) {
            float s    = __uint_as_float((unsigned)(key >> 32));
            unsigned a = (NTOT - 1) - (unsigned)((key >> 7) & 0x7FFFFu);
            int cls    = (int)(key & 0x7Fu);
            int b      = (int)(a >> 16);               // N_DIM = 65536
            float4 bx  = reinterpret_cast<const float4*>(boxes)[a];
            g_sbox[i] = bx;
            g_scat[i] = b * C_DIM + cls;
            g_sim[i]  = b;
            g_scls[i] = cls;
            g_ssc[i]  = s;
        } else {
            g_sbox[i] = make_float4(0.f, 0.f, 0.f, 0.f);
            g_scat[i] = -1; g_sim[i] = -1; g_scls[i] = -1; g_ssc[i] = 0.f;
        }
    }
    if (t == 0) g_M = M;
}

// ---------------- kernel 3: pairwise suppression bitmask ----------------
// block i computes row i; thread w computes the 64-bit word for j in [64w,64w+64)
__global__ void __launch_bounds__(64) k_mask() {
    int M = g_M;
    int i = blockIdx.x;
    if (i >= M) return;
    int w  = threadIdx.x;
    int j0 = w << 6;
    if (j0 >= M) return;

    float4 bi = g_sbox[i];
    int    ci = g_scat[i];
    float  ai = (bi.z - bi.x) * (bi.w - bi.y);

    unsigned long long bits = 0ULL;
    int jend = min(j0 + 64, M);
    for (int j = j0; j < jend; j++) {
        if (g_scat[j] == ci) {
            float4 bj = g_sbox[j];
            float iw = fminf(bi.z, bj.z) - fmaxf(bi.x, bj.x);
            float ih = fminf(bi.w, bj.w) - fmaxf(bi.y, bj.y);
            iw = fmaxf(iw, 0.f); ih = fmaxf(ih, 0.f);
            float inter = iw * ih;
            float aj  = (bj.z - bj.x) * (bj.w - bj.y);
            float uni = ai + aj - inter;
            float iou = inter / fmaxf(uni, 1e-12f);
            if (iou > NMS_TH) bits |= (1ULL << (j - j0));
        }
    }
    g_mask[(size_t)i * 64 + w] = bits;
}

// ---------------- kernel 4: fixed-point greedy NMS + output write ----------
// keep[i] = !exists j<i: keep[j] & sup(j,i). Dependencies form a DAG (j<i), so
// synchronous iteration converges to the unique greedy fixpoint; an unchanged
// round certifies the fixpoint. Typically 2-3 rounds here (sparse suppression).
__global__ void __launch_bounds__(1024) k_scan_out(float* __restrict__ out) {
    __shared__ unsigned long long kw[64];
    __shared__ unsigned char     nkb[TOPK];
    __shared__ int               changed;
    int t = threadIdx.x;
    int M = g_M;

    for (int i = t; i < TOPK; i += 1024) nkb[i] = 0;
    if (t < 64) {
        int lo = t << 6;
        unsigned long long wb;
        if (M >= lo + 64)      wb = ~0ULL;
        else if (M <= lo)      wb = 0ULL;
        else                   wb = (1ULL << (M - lo)) - 1ULL;
        kw[t] = wb;
    }
    __syncthreads();

    for (int round = 0; round < TOPK; round++) {
        if (t == 0) changed = 0;
        __syncthreads();
        for (int i = t; i < M; i += 1024) {
            const unsigned long long* row = &g_mask[(size_t)i * 64];
            int iw = i >> 6;
            unsigned long long supp = 0ULL;
            for (int w = 0; w < iw; w++) supp |= row[w] & kw[w];
            supp |= row[iw] & kw[iw] & ((1ULL << (i & 63)) - 1ULL);
            nkb[i] = (supp == 0ULL) ? 1 : 0;
        }
        __syncthreads();
        if (t < 64) {
            unsigned long long wb = 0ULL;
            const unsigned char* p = &nkb[t << 6];
            #pragma unroll 8
            for (int b = 0; b < 64; b++) wb |= ((unsigned long long)p[b]) << b;
            if (wb != kw[t]) { kw[t] = wb; changed = 1; }
        }
        __syncthreads();
        if (!changed) break;
    }

    // output: [img(4096) | boxes(4096*4) | classes(4096) | scores(4096)] as f32
    float* o_img = out;
    float* o_box = out + TOPK;
    float* o_cls = out + TOPK + TOPK * 4;
    float* o_sc  = out + TOPK + TOPK * 4 + TOPK;
    for (int i = t; i < TOPK; i += 1024) {
        bool k = (kw[i >> 6] >> (i & 63)) & 1ULL;
        float4 bx = g_sbox[i];
        o_img[i]       = k ? (float)g_sim[i]  : -1.0f;
        o_box[i*4 + 0] = k ? bx.x : 0.0f;
        o_box[i*4 + 1] = k ? bx.y : 0.0f;
        o_box[i*4 + 2] = k ? bx.z : 0.0f;
        o_box[i*4 + 3] = k ? bx.w : 0.0f;
        o_cls[i]       = k ? (float)g_scls[i] : -1.0f;
        o_sc[i]        = k ? g_ssc[i]         : 0.0f;
    }
}

// ---------------- launcher ----------------
extern "C" void kernel_launch(void* const* d_in, const int* in_sizes, int n_in,
                              void* d_out, int out_size) {
    const float* logits = (const float*)d_in[0];
    const float* boxes  = (const float*)d_in[1];
    float* out = (float*)d_out;

    k_init<<<1, 1>>>();
    k_reduce<<<NTOT / 8, 256>>>(logits);   // 8 warps/block, 1 warp/anchor
    k_sort<<<1, 1024>>>(boxes);
    k_mask<<<TOPK, 64>>>();
    k_scan_out<<<1, 1024>>>(out);
}

// round 6
// speedup vs baseline: 1.2321x; 1.2321x over previous
#include <cuda_runtime.h>
#include <cuda_bf16.h>
#include <math_constants.h>

#define B_DIM 8
#define N_DIM 65536
#define C_DIM 80
#define NTOT (B_DIM * N_DIM)          // 524288 = 2^19
#define TOPK 4096
#define CONF_TH 4.0f
#define NMS_TH 0.5f

// ---------------- device scratch (no allocation allowed) ----------------
__device__ unsigned int        g_cnt;          // zero-initialized; reset at end of k_scan_out
__device__ unsigned long long  g_keys[TOPK];
__device__ int                 g_M;
__device__ float4              g_sbox[TOPK];
__device__ int                 g_scat[TOPK];
__device__ int                 g_sim[TOPK];
__device__ int                 g_scls[TOPK];
__device__ float               g_ssc[TOPK];
__device__ unsigned long long  g_mask[(size_t)TOPK * 64];   // only lower triangle used

// ---------------- kernel 1: per-anchor max/argmax + threshold compaction ----
// One warp per anchor; lanes 0..19 each load a float4 (4 classes).
__device__ __forceinline__ void comb(float& s, int& c, float s2, int c2) {
    if (s2 > s || (s2 == s && c2 < c)) { s = s2; c = c2; }
}

__global__ void __launch_bounds__(256) k_reduce(const float* __restrict__ logits) {
    int wid  = (blockIdx.x * blockDim.x + threadIdx.x) >> 5;
    int lane = threadIdx.x & 31;

    float s = -CUDART_INF_F;
    int   c = 127;
    if (lane < 20) {
        float4 v = __ldcs(reinterpret_cast<const float4*>(logits) + (size_t)wid * 20 + lane);
        s = v.x; c = lane * 4;
        comb(s, c, v.y, lane * 4 + 1);
        comb(s, c, v.z, lane * 4 + 2);
        comb(s, c, v.w, lane * 4 + 3);
    }

    #pragma unroll
    for (int off = 16; off > 0; off >>= 1) {
        float s2 = __shfl_down_sync(0xFFFFFFFFu, s, off);
        int   c2 = __shfl_down_sync(0xFFFFFFFFu, c, off);
        comb(s, c, s2, c2);   // lower lane = lower class on ties
    }

    if (lane == 0 && s > CONF_TH) {
        unsigned pos = atomicAdd(&g_cnt, 1u);
        if (pos < TOPK) {
            unsigned long long key =
                ((unsigned long long)__float_as_uint(s) << 32) |
                ((unsigned long long)(unsigned)((NTOT - 1) - wid) << 7) |
                (unsigned long long)(unsigned)c;
            g_keys[pos] = key;
        }
    }
}

// ---------------- kernel 2: rank-based sort (keys distinct) + scatter --------
// rank(i) = #{j : key[j] > key[i]}  -> sorted position. Order-independent of
// the nondeterministic atomic compaction order => deterministic output.
// 4 blocks x 1024 threads cover all TOPK slots: g < M ranks+scatters,
// g >= M writes padding defaults (disjoint target positions).
__global__ void __launch_bounds__(1024) k_rank(const float* __restrict__ boxes) {
    __shared__ unsigned long long sk[TOPK];
    int t = threadIdx.x;
    int M = (int)min(g_cnt, (unsigned)TOPK);

    for (int i = t; i < M; i += 1024) sk[i] = g_keys[i];
    __syncthreads();

    int g = blockIdx.x * 1024 + t;
    if (g == 0) g_M = M;

    if (g < M) {
        unsigned long long me = sk[g];
        int r = 0, j = 0;
        for (; j + 4 <= M; j += 4) {
            r += (sk[j]     > me);
            r += (sk[j + 1] > me);
            r += (sk[j + 2] > me);
            r += (sk[j + 3] > me);
        }
        for (; j < M; j++) r += (sk[j] > me);

        float s    = __uint_as_float((unsigned)(me >> 32));
        unsigned a = (NTOT - 1) - (unsigned)((me >> 7) & 0x7FFFFu);
        int cls    = (int)(me & 0x7Fu);
        int b      = (int)(a >> 16);                 // N_DIM = 65536
        float4 bx  = reinterpret_cast<const float4*>(boxes)[a];
        g_sbox[r] = bx;
        g_scat[r] = b * C_DIM + cls;
        g_sim[r]  = b;
        g_scls[r] = cls;
        g_ssc[r]  = s;
    } else {
        g_sbox[g] = make_float4(0.f, 0.f, 0.f, 0.f);
        g_scat[g] = -1; g_sim[g] = -1; g_scls[g] = -1; g_ssc[g] = 0.f;
    }
}

// ---------------- kernel 3: lower-triangle suppression bitmask ---------------
// Block = row i (8 warps). Warp owns word w; lane owns j = 64w + h*32 + lane
// (coalesced), word assembled via ballot. Only words w <= i>>6 are computed
// (the scan never reads the upper triangle).
__global__ void __launch_bounds__(256) k_mask() {
    int M = g_M;
    int i = blockIdx.x;
    if (i >= M) return;
    int warp = threadIdx.x >> 5;
    int lane = threadIdx.x & 31;

    float4 bi = g_sbox[i];
    int    ci = g_scat[i];
    float  ai = (bi.z - bi.x) * (bi.w - bi.y);

    int nw = (i >> 6) + 1;
    for (int w = warp; w < nw; w += 8) {
        int j0 = w << 6;
        unsigned long long bits = 0ULL;
        #pragma unroll
        for (int h = 0; h < 2; h++) {
            int j = j0 + h * 32 + lane;
            bool sup = false;
            if (j < M && __ldg(&g_scat[j]) == ci) {
                float4 bj = g_sbox[j];
                float iw = fminf(bi.z, bj.z) - fmaxf(bi.x, bj.x);
                float ih = fminf(bi.w, bj.w) - fmaxf(bi.y, bj.y);
                iw = fmaxf(iw, 0.f); ih = fmaxf(ih, 0.f);
                float inter = iw * ih;
                float aj  = (bj.z - bj.x) * (bj.w - bj.y);
                float iou = inter / fmaxf(ai + aj - inter, 1e-12f);
                sup = iou > NMS_TH;
            }
            unsigned b = __ballot_sync(0xFFFFFFFFu, sup);
            bits |= ((unsigned long long)b) << (h * 32);
        }
        if (lane == 0) g_mask[(size_t)i * 64 + w] = bits;
    }
}

// ---------------- kernel 4: fixed-point greedy NMS + output ------------------
// keep[i] = !exists j<i: keep[j] & sup(j,i). DAG over j<i => synchronous
// iteration converges to the unique greedy fixpoint (unchanged round = done).
__global__ void __launch_bounds__(1024) k_scan_out(float* __restrict__ out) {
    __shared__ unsigned long long kw[64];
    __shared__ unsigned char     nkb[TOPK];
    __shared__ int               changed;
    int t = threadIdx.x;
    int M = g_M;

    for (int i = t; i < TOPK; i += 1024) nkb[i] = 0;
    if (t < 64) {
        int lo = t << 6;
        unsigned long long wb;
        if (M >= lo + 64)      wb = ~0ULL;
        else if (M <= lo)      wb = 0ULL;
        else                   wb = (1ULL << (M - lo)) - 1ULL;
        kw[t] = wb;
    }
    __syncthreads();

    for (int round = 0; round < TOPK; round++) {
        if (t == 0) changed = 0;
        __syncthreads();
        for (int i = t; i < M; i += 1024) {
            const unsigned long long* row = &g_mask[(size_t)i * 64];
            int iw = i >> 6;
            unsigned long long supp = 0ULL;
            for (int w = 0; w < iw; w++) supp |= row[w] & kw[w];
            supp |= row[iw] & kw[iw] & ((1ULL << (i & 63)) - 1ULL);
            nkb[i] = (supp == 0ULL) ? 1 : 0;
        }
        __syncthreads();
        if (t < 64) {
            unsigned long long wb = 0ULL;
            const unsigned char* p = &nkb[t << 6];
            #pragma unroll 8
            for (int b = 0; b < 64; b++) wb |= ((unsigned long long)p[b]) << b;
            if (wb != kw[t]) { kw[t] = wb; changed = 1; }
        }
        __syncthreads();
        if (!changed) break;
    }

    // output: [img(4096) | boxes(4096*4) | classes(4096) | scores(4096)] f32
    float* o_img = out;
    float* o_box = out + TOPK;
    float* o_cls = out + TOPK + TOPK * 4;
    float* o_sc  = out + TOPK + TOPK * 4 + TOPK;
    for (int i = t; i < TOPK; i += 1024) {
        bool k = (kw[i >> 6] >> (i & 63)) & 1ULL;
        float4 bx = g_sbox[i];
        o_img[i]       = k ? (float)g_sim[i]  : -1.0f;
        o_box[i*4 + 0] = k ? bx.x : 0.0f;
        o_box[i*4 + 1] = k ? bx.y : 0.0f;
        o_box[i*4 + 2] = k ? bx.z : 0.0f;
        o_box[i*4 + 3] = k ? bx.w : 0.0f;
        o_cls[i]       = k ? (float)g_scls[i] : -1.0f;
        o_sc[i]        = k ? g_ssc[i]         : 0.0f;
    }

    if (t == 0) g_cnt = 0u;   // reset for next launch (initial value is 0 too)
}

// ---------------- launcher ----------------
extern "C" void kernel_launch(void* const* d_in, const int* in_sizes, int n_in,
                              void* d_out, int out_size) {
    const float* logits = (const float*)d_in[0];
    const float* boxes  = (const float*)d_in[1];
    float* out = (float*)d_out;

    k_reduce<<<NTOT / 8, 256>>>(logits);   // 1 warp per anchor
    k_rank<<<TOPK / 1024, 1024>>>(boxes);  // rank-sort + scatter + padding
    k_mask<<<TOPK, 256>>>();               // lower-triangle suppression bits
    k_scan_out<<<1, 1024>>>(out);          // greedy fixpoint + outputs
}

// round 7
// speedup vs baseline: 1.9318x; 1.5679x over previous
#include <cuda_runtime.h>
#include <cuda_bf16.h>
#include <math_constants.h>

#define B_DIM 8
#define N_DIM 65536
#define C_DIM 80
#define NTOT (B_DIM * N_DIM)          // 524288 = 2^19
#define TOPK 4096
#define CONF_TH 4.0f
#define NMS_TH 0.5f

// mono(4.0f): 0x40800000 ^ 0x80000000 (positive float -> ordered uint)
#define MONO_TH 0xC0800000u

// ---------------- device scratch (no allocation allowed) ----------------
__device__ unsigned int        g_cnt;      // zero-init; reset at end of k_scan_out
__device__ unsigned int        g_ncont;    // contested-row count; same reset
__device__ unsigned long long  g_keys[TOPK];
__device__ int                 g_M;
__device__ int                 g_cont[TOPK];
__device__ float4              g_sbox[TOPK];
__device__ int                 g_scat[TOPK];
__device__ int                 g_sim[TOPK];
__device__ int                 g_scls[TOPK];
__device__ float               g_ssc[TOPK];
__device__ unsigned long long  g_mask[(size_t)TOPK * 64];   // lower triangle, diag word pre-masked

// ---------------- kernel 1: max/argmax over C=80 + threshold compaction -----
// Block = 256 threads = 64 anchors. Each thread: 5 independent coalesced
// LDG.128 (high MLP), fold each float4 into a monotone u64 key
// (mono(score)<<32 | (127-cls)), stage in smem, 4-lane groups max-reduce
// the 20 keys of one anchor. u64-max == (max score, tie -> lowest class).
__global__ void __launch_bounds__(256) k_reduce(const float* __restrict__ logits) {
    __shared__ unsigned long long ks[1280];
    int t = threadIdx.x;
    size_t qbase = (size_t)blockIdx.x * 1280;   // float4 index base (64 anchors * 20)

    const float4* lp = reinterpret_cast<const float4*>(logits);

    float4 v[5];
    #pragma unroll
    for (int k = 0; k < 5; k++)
        v[k] = __ldcs(lp + qbase + t + k * 256);

    #pragma unroll
    for (int k = 0; k < 5; k++) {
        int q = t + k * 256;                    // 0..1279 within block
        int sub = q - (q / 20) * 20;            // q % 20
        float s = v[k].x; int c0 = 0;
        if (v[k].y > s) { s = v[k].y; c0 = 1; }
        if (v[k].z > s) { s = v[k].z; c0 = 2; }
        if (v[k].w > s) { s = v[k].w; c0 = 3; }
        int cls = sub * 4 + c0;
        unsigned u = __float_as_uint(s);
        u ^= ((unsigned)((int)u >> 31)) | 0x80000000u;   // monotone map
        ks[q] = ((unsigned long long)u << 32) | (unsigned)(127 - cls);
    }
    __syncthreads();

    // 4 threads per anchor, 5 keys each
    int a   = t >> 2;                           // local anchor 0..63
    int grp = t & 3;
    const unsigned long long* p = &ks[a * 20 + grp * 5];
    unsigned long long key = p[0];
    key = max(key, p[1]); key = max(key, p[2]);
    key = max(key, p[3]); key = max(key, p[4]);
    key = max(key, __shfl_down_sync(0xFFFFFFFFu, key, 2));
    key = max(key, __shfl_down_sync(0xFFFFFFFFu, key, 1));

    if (grp == 0) {
        unsigned mono = (unsigned)(key >> 32);
        if (mono > MONO_TH) {                   // s > 4.0 (all such s positive)
            unsigned sbits = mono ^ 0x80000000u;
            int cls = 127 - (int)(unsigned)(key & 0xFFFFFFFFu);
            int wid = blockIdx.x * 64 + a;
            unsigned pos = atomicAdd(&g_cnt, 1u);
            if (pos < TOPK) {
                g_keys[pos] =
                    ((unsigned long long)sbits << 32) |
                    ((unsigned long long)(unsigned)((NTOT - 1) - wid) << 7) |
                    (unsigned long long)(unsigned)cls;
            }
        }
    }
}

// ---------------- kernel 2: rank-based sort (keys distinct) + scatter --------
__global__ void __launch_bounds__(1024) k_rank(const float* __restrict__ boxes) {
    __shared__ unsigned long long sk[TOPK];
    int t = threadIdx.x;
    int M = (int)min(g_cnt, (unsigned)TOPK);

    for (int i = t; i < M; i += 1024) sk[i] = g_keys[i];
    __syncthreads();

    int g = blockIdx.x * 1024 + t;
    if (g == 0) g_M = M;

    if (g < M) {
        unsigned long long me = sk[g];
        int r = 0, j = 0;
        for (; j + 4 <= M; j += 4) {
            r += (sk[j]     > me);
            r += (sk[j + 1] > me);
            r += (sk[j + 2] > me);
            r += (sk[j + 3] > me);
        }
        for (; j < M; j++) r += (sk[j] > me);

        float s    = __uint_as_float((unsigned)(me >> 32));
        unsigned a = (NTOT - 1) - (unsigned)((me >> 7) & 0x7FFFFu);
        int cls    = (int)(me & 0x7Fu);
        int b      = (int)(a >> 16);                 // N_DIM = 65536
        float4 bx  = reinterpret_cast<const float4*>(boxes)[a];
        g_sbox[r] = bx;
        g_scat[r] = b * C_DIM + cls;
        g_sim[r]  = b;
        g_scls[r] = cls;
        g_ssc[r]  = s;
    } else {
        g_sbox[g] = make_float4(0.f, 0.f, 0.f, 0.f);
        g_scat[g] = -1; g_sim[g] = -1; g_scls[g] = -1; g_ssc[g] = 0.f;
    }
}

// ---------------- kernel 3: lower-triangle suppression bitmask ---------------
// Block = row i. Warp owns word w; lane owns j (coalesced); ballot assembles
// the word. The diagonal word is pre-masked to strictly j<i (kills self-bit).
// Rows with ANY suppressor bit are appended to the contested list.
__global__ void __launch_bounds__(256) k_mask() {
    __shared__ int any;
    int M = g_M;
    int i = blockIdx.x;
    if (i >= M) return;
    int warp = threadIdx.x >> 5;
    int lane = threadIdx.x & 31;
    if (threadIdx.x == 0) any = 0;
    __syncthreads();

    float4 bi = g_sbox[i];
    int    ci = g_scat[i];
    float  ai = (bi.z - bi.x) * (bi.w - bi.y);

    int iw = i >> 6;
    for (int w = warp; w <= iw; w += 8) {
        int j0 = w << 6;
        unsigned long long bits = 0ULL;
        #pragma unroll
        for (int h = 0; h < 2; h++) {
            int j = j0 + h * 32 + lane;
            bool sup = false;
            if (j < M && __ldg(&g_scat[j]) == ci) {
                float4 bj = g_sbox[j];
                float w_ = fminf(bi.z, bj.z) - fmaxf(bi.x, bj.x);
                float h_ = fminf(bi.w, bj.w) - fmaxf(bi.y, bj.y);
                w_ = fmaxf(w_, 0.f); h_ = fmaxf(h_, 0.f);
                float inter = w_ * h_;
                float aj  = (bj.z - bj.x) * (bj.w - bj.y);
                float iou = inter / fmaxf(ai + aj - inter, 1e-12f);
                sup = iou > NMS_TH;
            }
            unsigned b = __ballot_sync(0xFFFFFFFFu, sup);
            bits |= ((unsigned long long)b) << (h * 32);
        }
        if (w == iw) {
            int r = i & 63;
            bits &= r ? ((1ULL << r) - 1ULL) : 0ULL;   // strictly lower triangle
        }
        if (lane == 0) {
            g_mask[(size_t)i * 64 + w] = bits;
            if (bits) atomicOr(&any, 1);
        }
    }
    __syncthreads();
    if (threadIdx.x == 0 && any) {
        unsigned pos = atomicAdd(&g_ncont, 1u);
        g_cont[pos] = i;
    }
}

// ---------------- kernel 4: contested-only greedy fixpoint + output ----------
// keep[i]=1 is stable for any row with an empty mask; only contested rows
// (those with >=1 suppressor bit) can change. Iterate the synchronous
// fixpoint over that tiny set; an unchanged round certifies convergence
// (dependencies form a DAG over j<i => unique greedy fixpoint).
__global__ void __launch_bounds__(1024) k_scan_out(float* __restrict__ out) {
    __shared__ unsigned long long kw[64];
    __shared__ unsigned char     nkb[TOPK];
    __shared__ int               changed;
    int t = threadIdx.x;
    int M  = g_M;
    int nc = (int)g_ncont;

    if (t < 64) {
        int lo = t << 6;
        unsigned long long wb;
        if (M >= lo + 64)      wb = ~0ULL;
        else if (M <= lo)      wb = 0ULL;
        else                   wb = (1ULL << (M - lo)) - 1ULL;
        kw[t] = wb;
    }
    __syncthreads();

    for (int round = 0; round < TOPK && nc; round++) {
        if (t == 0) changed = 0;
        __syncthreads();
        for (int c = t; c < nc; c += 1024) {
            int i = g_cont[c];
            const unsigned long long* row = &g_mask[(size_t)i * 64];
            int iw = i >> 6;
            unsigned long long supp = 0ULL;
            for (int w = 0; w <= iw; w++) supp |= row[w] & kw[w];
            nkb[c] = (supp == 0ULL) ? 1 : 0;
        }
        __syncthreads();
        for (int c = t; c < nc; c += 1024) {
            int i = g_cont[c];
            unsigned long long bit = 1ULL << (i & 63);
            bool cur = (kw[i >> 6] & bit) != 0ULL;
            bool nk  = nkb[c] != 0;
            if (cur != nk) {
                if (nk) atomicOr (&kw[i >> 6], bit);
                else    atomicAnd(&kw[i >> 6], ~bit);
                changed = 1;
            }
        }
        __syncthreads();
        if (!changed) break;
        __syncthreads();
    }

    // output: [img(4096) | boxes(4096*4) | classes(4096) | scores(4096)] f32
    float* o_img = out;
    float* o_box = out + TOPK;
    float* o_cls = out + TOPK + TOPK * 4;
    float* o_sc  = out + TOPK + TOPK * 4 + TOPK;
    for (int i = t; i < TOPK; i += 1024) {
        bool k = (kw[i >> 6] >> (i & 63)) & 1ULL;
        float4 bx = g_sbox[i];
        o_img[i]       = k ? (float)g_sim[i]  : -1.0f;
        o_box[i*4 + 0] = k ? bx.x : 0.0f;
        o_box[i*4 + 1] = k ? bx.y : 0.0f;
        o_box[i*4 + 2] = k ? bx.z : 0.0f;
        o_box[i*4 + 3] = k ? bx.w : 0.0f;
        o_cls[i]       = k ? (float)g_scls[i] : -1.0f;
        o_sc[i]        = k ? g_ssc[i]         : 0.0f;
    }

    if (t == 0) { g_cnt = 0u; g_ncont = 0u; }   // restore launch-entry invariant
}

// ---------------- launcher ----------------
extern "C" void kernel_launch(void* const* d_in, const int* in_sizes, int n_in,
                              void* d_out, int out_size) {
    const float* logits = (const float*)d_in[0];
    const float* boxes  = (const float*)d_in[1];
    float* out = (float*)d_out;

    k_reduce<<<NTOT / 64, 256>>>(logits);  // 64 anchors/block, 5 LDG.128/thread
    k_rank<<<TOPK / 1024, 1024>>>(boxes);  // rank-sort + scatter + padding
    k_mask<<<TOPK, 256>>>();               // lower-triangle bits + contested list
    k_scan_out<<<1, 1024>>>(out);          // contested-only fixpoint + outputs
}